// round 14
// baseline (speedup 1.0000x reference)
#include <cuda_runtime.h>
#include <cstdint>

#define NUSERS 100000
#define NITEMS 200000
#define NNODES 300000
#define DIM 64
#define ROWSTRIDE 256            // LEVELS * DIM
#define NNZ_E 1200000
#define NHOPS 3
#define INV_MESS_KEEP 1.1111112f // fp32(1/0.9)

#define MASK_WORDS 600000        // NNODES*DIM/32 bits per hop
#define SPMM_BLOCKS 37500        // NNODES rows / 8 rows-per-block

#define SCAN_BLK 1024
#define NBLK ((NNODES + SCAN_BLK - 1) / SCAN_BLK)   // 293

// Scratch (__device__ globals; no allocations allowed). ~28 MB total.
__device__ unsigned g_deg[NNODES];        // degree histogram, then scatter cursor
__device__ unsigned g_rowptr[NNODES + 1]; // CSR row pointers
__device__ unsigned g_bsum[NBLK];         // scan block sums
__device__ float4   g_ew3[NNZ_E];         // CSR-ordered {w_hop0, w_hop1, w_hop2, bitcast(col)}
__device__ unsigned g_mask[NHOPS * MASK_WORDS];  // message-dropout keep bits

// ---------------------------------------------------------------------------
// Threefry-2x32 (JAX partitionable mode) — validated bit-exact (rel_err 7e-8)
// ---------------------------------------------------------------------------
__host__ __device__ __forceinline__ uint32_t rotl32(uint32_t x, int r) {
#ifdef __CUDA_ARCH__
    return __funnelshift_l(x, x, r);
#else
    return (x << r) | (x >> (32 - r));
#endif
}

__host__ __device__ __forceinline__ void threefry2x32(
    uint32_t k0, uint32_t k1, uint32_t x0, uint32_t x1,
    uint32_t& o0, uint32_t& o1)
{
    uint32_t ks2 = k0 ^ k1 ^ 0x1BD11BDAu;
    x0 += k0; x1 += k1;
#define TF_R(r) { x0 += x1; x1 = rotl32(x1, r); x1 ^= x0; }
    TF_R(13) TF_R(15) TF_R(26) TF_R(6)
    x0 += k1;  x1 += ks2 + 1u;
    TF_R(17) TF_R(29) TF_R(16) TF_R(24)
    x0 += ks2; x1 += k0 + 2u;
    TF_R(13) TF_R(15) TF_R(26) TF_R(6)
    x0 += k0;  x1 += k1 + 3u;
    TF_R(17) TF_R(29) TF_R(16) TF_R(24)
    x0 += k1;  x1 += ks2 + 4u;
    TF_R(13) TF_R(15) TF_R(26) TF_R(6)
    x0 += ks2; x1 += k0 + 5u;
#undef TF_R
    o0 = x0; o1 = x1;
}

__device__ __forceinline__ uint32_t tf_bits(uint32_t k0, uint32_t k1, uint32_t i) {
    uint32_t a, b;
    threefry2x32(k0, k1, 0u, i, a, b);
    return a ^ b;
}

__device__ __forceinline__ float bits_to_u01(uint32_t bits) {
    return __uint_as_float((bits >> 9) | 0x3f800000u) - 1.0f;
}

// mask generation for `nwords` consecutive words starting at `word0`
// (one ballot-packed word per iteration; element j = word*32 + lane)
__device__ __forceinline__ void mask_words(unsigned word0, unsigned nwords,
                                           uint32_t k0, uint32_t k1,
                                           unsigned* __restrict__ dst,
                                           unsigned lane)
{
    for (unsigned k = 0; k < nwords; k++) {
        unsigned w = word0 + k;
        if (w >= MASK_WORDS) return;
        unsigned j = w * 32u + lane;
        float u = bits_to_u01(tf_bits(k0, k1, j));
        unsigned bits = __ballot_sync(0xFFFFFFFFu, u < 0.9f);
        if (lane == 0u) dst[w] = bits;
    }
}

// ---------------------------------------------------------------------------
// CSR build: zero -> histogram -> 2-level exclusive scan
// ---------------------------------------------------------------------------
__global__ void __launch_bounds__(256)
k_zero()
{
    unsigned i = blockIdx.x * blockDim.x + threadIdx.x;
    if (i < NNODES) g_deg[i] = 0u;
}

__global__ void __launch_bounds__(256)
k_hist(const int* __restrict__ rows)
{
    unsigned e = blockIdx.x * blockDim.x + threadIdx.x;
    if (e >= NNZ_E) return;
    atomicAdd(&g_deg[rows[e]], 1u);
}

__global__ void __launch_bounds__(256)
k_scan1()
{
    __shared__ unsigned warp_sums[8];
    unsigned b = blockIdx.x;
    unsigned base = b * SCAN_BLK + threadIdx.x * 4u;
    unsigned v[4];
#pragma unroll
    for (int i = 0; i < 4; i++) {
        unsigned idx = base + i;
        v[i] = (idx < NNODES) ? g_deg[idx] : 0u;
    }
    unsigned tsum = v[0] + v[1] + v[2] + v[3];
    unsigned lane = threadIdx.x & 31u, wid = threadIdx.x >> 5;
    unsigned x = tsum;
#pragma unroll
    for (int o = 1; o < 32; o <<= 1) {
        unsigned y = __shfl_up_sync(0xFFFFFFFFu, x, o);
        if (lane >= (unsigned)o) x += y;
    }
    if (lane == 31) warp_sums[wid] = x;
    __syncthreads();
    if (wid == 0) {
        unsigned s = (lane < 8) ? warp_sums[lane] : 0u;
#pragma unroll
        for (int o = 1; o < 8; o <<= 1) {
            unsigned y = __shfl_up_sync(0xFFFFFFFFu, s, o);
            if (lane >= (unsigned)o) s += y;
        }
        if (lane < 8) warp_sums[lane] = s;
    }
    __syncthreads();
    unsigned warp_off = (wid > 0) ? warp_sums[wid - 1] : 0u;
    unsigned run = warp_off + (x - tsum);
#pragma unroll
    for (int i = 0; i < 4; i++) {
        unsigned idx = base + i;
        if (idx < NNODES) g_rowptr[idx] = run;
        run += v[i];
    }
    if (threadIdx.x == 255) g_bsum[b] = warp_sums[7];
}

__global__ void __launch_bounds__(512)
k_scan2()
{
    __shared__ unsigned sm[512];
    unsigned t = threadIdx.x;
    sm[t] = (t < NBLK) ? g_bsum[t] : 0u;
    __syncthreads();
#pragma unroll
    for (int o = 1; o < 512; o <<= 1) {
        unsigned y = (t >= (unsigned)o) ? sm[t - o] : 0u;
        __syncthreads();
        sm[t] += y;
        __syncthreads();
    }
    if (t < NBLK) g_bsum[t] = (t == 0) ? 0u : sm[t - 1];
}

__global__ void __launch_bounds__(256)
k_scan3()
{
    unsigned i = blockIdx.x * blockDim.x + threadIdx.x;
    if (i < NNODES) {
        g_rowptr[i] += g_bsum[i >> 10];
        g_deg[i] = 0u;                     // reuse as scatter cursor
    }
    if (i == 0) g_rowptr[NNODES] = NNZ_E;
}

// ---------------------------------------------------------------------------
// prep: 320-thread blocks. Warps 0-7: CSR scatter + all-hop edge dropout RNG.
// Warps 8-9: hop-0 message mask (64 words per warp -> long-lived, no churn).
// ---------------------------------------------------------------------------
#define PREP_BLOCKS 4688   // ceil(NNZ_E / 256)
__global__ void __launch_bounds__(320)
k_prep(const int* __restrict__ rows, const int* __restrict__ cols,
       const float* __restrict__ vals,
       uint32_t ka0, uint32_t ka1, uint32_t kb0, uint32_t kb1,
       uint32_t kc0, uint32_t kc1, uint32_t km0, uint32_t km1)
{
    unsigned tid = threadIdx.x;
    unsigned b = blockIdx.x;
    if (tid < 256u) {
        unsigned e = b * 256u + tid;
        if (e >= NNZ_E) return;
        int r = rows[e];
        float v2 = vals[e] * 2.0f;
        uint32_t b0 = tf_bits(ka0, ka1, e);
        uint32_t b1 = tf_bits(kb0, kb1, e);
        uint32_t b2 = tf_bits(kc0, kc1, e);
        float4 ew;
        ew.x = (b0 & 0x80000000u) ? v2 : 0.0f;   // u >= 0.5 <=> top bit (exact)
        ew.y = (b1 & 0x80000000u) ? v2 : 0.0f;
        ew.z = (b2 & 0x80000000u) ? v2 : 0.0f;
        ew.w = __int_as_float(cols[e]);
        unsigned pos = g_rowptr[r] + atomicAdd(&g_deg[r], 1u);
        g_ew3[pos] = ew;
    } else {
        unsigned w = (tid >> 5) - 8u;            // 0 or 1
        unsigned lane = tid & 31u;
        unsigned slot = b * 2u + w;              // [0, 9376)
        mask_words(slot * 64u, 64u, km0, km1, g_mask, lane);
    }
}

// ---------------------------------------------------------------------------
// hop kernel: 320-thread blocks (HOP<2) or 256 (HOP==2).
// Warps 0-7: RNG-free SpMM + mask apply (reads g_mask[HOP]).
// Warps 8-9 (HOP<2 only): generate mask for HOP+1 (8 words per warp).
// ---------------------------------------------------------------------------
template <int HOP>
__global__ void __launch_bounds__(320)
k_hop(const float* __restrict__ ue, const float* __restrict__ ie,
      float* __restrict__ out, uint32_t kn0, uint32_t kn1)
{
    unsigned tid = threadIdx.x;
    unsigned lane = tid & 31u;

    if (HOP < 2 && tid >= 256u) {
        unsigned w = (tid >> 5) - 8u;            // 0 or 1
        unsigned slot = blockIdx.x * 2u + w;     // [0, 75000)
        mask_words(slot * 8u, 8u, kn0, kn1, g_mask + (HOP + 1) * MASK_WORDS, lane);
        return;
    }

    unsigned r = blockIdx.x * 8u + (tid >> 5);   // row
    if (r >= NNODES) return;

    // issue all front loads immediately (independent, scoreboarded)
    unsigned start = __ldg(&g_rowptr[r]);
    unsigned end   = __ldg(&g_rowptr[r + 1]);
    unsigned mword = __ldg(&g_mask[HOP * MASK_WORDS + r * 2u + (lane >> 4)]);

    unsigned p0 = 2u * (lane & 15u);
    float keep0 = ((mword >> p0) & 1u)        ? INV_MESS_KEEP : 0.0f;
    float keep1 = ((mword >> (p0 + 1u)) & 1u) ? INV_MESS_KEEP : 0.0f;

    float2 acc = make_float2(0.f, 0.f);
    const float* src_base = out + (size_t)HOP * DIM;   // when HOP>0

    auto wsel = [](const float4& e) {
        return (HOP == 0) ? e.x : (HOP == 1) ? e.y : e.z;
    };
    auto srow_of = [&](int c) -> const float* {
        if (HOP == 0)
            return (c < NUSERS) ? (ue + (size_t)c * DIM)
                                : (ie + (size_t)(c - NUSERS) * DIM);
        return src_base + (size_t)c * ROWSTRIDE;
    };

    const float4 z4 = make_float4(0.f, 0.f, 0.f, 0.f);
    for (unsigned p = start; p < end; p += 4u) {
        float4 e0 = g_ew3[p];
        float4 e1 = (p + 1u < end) ? g_ew3[p + 1u] : z4;
        float4 e2 = (p + 2u < end) ? g_ew3[p + 2u] : z4;
        float4 e3 = (p + 3u < end) ? g_ew3[p + 3u] : z4;
        float w0 = wsel(e0), w1 = wsel(e1), w2 = wsel(e2), w3 = wsel(e3);
        float2 s0 = make_float2(0.f, 0.f), s1 = s0, s2 = s0, s3 = s0;
        if (w0 != 0.f) s0 = *reinterpret_cast<const float2*>(srow_of(__float_as_int(e0.w)) + lane * 2u);
        if (w1 != 0.f) s1 = *reinterpret_cast<const float2*>(srow_of(__float_as_int(e1.w)) + lane * 2u);
        if (w2 != 0.f) s2 = *reinterpret_cast<const float2*>(srow_of(__float_as_int(e2.w)) + lane * 2u);
        if (w3 != 0.f) s3 = *reinterpret_cast<const float2*>(srow_of(__float_as_int(e3.w)) + lane * 2u);
        acc.x += w0 * s0.x + w1 * s1.x + w2 * s2.x + w3 * s3.x;
        acc.y += w0 * s0.y + w1 * s1.y + w2 * s2.y + w3 * s3.y;
    }

    float2 res;
    res.x = acc.x * keep0;
    res.y = acc.y * keep1;

    float* orow = out + (size_t)r * ROWSTRIDE;
    *reinterpret_cast<float2*>(orow + (size_t)(HOP + 1) * DIM + lane * 2u) = res;

    if (HOP == 0) {
        const float* erow = (r < NUSERS) ? (ue + (size_t)r * DIM)
                                         : (ie + (size_t)(r - NUSERS) * DIM);
        float2 e0 = *reinterpret_cast<const float2*>(erow + lane * 2u);
        *reinterpret_cast<float2*>(orow + lane * 2u) = e0;
    }
}

// ---------------------------------------------------------------------------
// Launch (single stream; masks ride inside prep/hop kernels as extra warps)
// ---------------------------------------------------------------------------
extern "C" void kernel_launch(void* const* d_in, const int* in_sizes, int n_in,
                              void* d_out, int out_size)
{
    const float* ue = nullptr; const float* ie = nullptr;
    const float* vals = nullptr; const int* rows = nullptr; const int* cols = nullptr;
    int nnz_seen = 0;
    for (int i = 0; i < n_in; i++) {
        if (in_sizes[i] == NUSERS * DIM)      ue = (const float*)d_in[i];
        else if (in_sizes[i] == NITEMS * DIM) ie = (const float*)d_in[i];
        else if (in_sizes[i] == NNZ_E) {
            if (nnz_seen == 0)      vals = (const float*)d_in[i];
            else if (nnz_seen == 1) rows = (const int*)d_in[i];
            else                    cols = (const int*)d_in[i];
            nnz_seen++;
        }
    }
    float* out = (float*)d_out;

    // JAX key derivation (validated): base=(0,42); hk=cipher(base,(0,hop));
    // ke=cipher(hk,(0,0)), km=cipher(hk,(0,1))
    uint32_t ke0[NHOPS], ke1[NHOPS], km0[NHOPS], km1[NHOPS];
    for (int h = 0; h < NHOPS; h++) {
        uint32_t h0, h1;
        threefry2x32(0u, 42u, 0u, (uint32_t)h, h0, h1);
        threefry2x32(h0, h1, 0u, 0u, ke0[h], ke1[h]);
        threefry2x32(h0, h1, 0u, 1u, km0[h], km1[h]);
    }

    const int TB = 256;
    unsigned gb_node = (NNODES + TB - 1) / TB;
    unsigned gb_edge = (NNZ_E + TB - 1) / TB;

    k_zero<<<gb_node, TB>>>();
    k_hist<<<gb_edge, TB>>>(rows);
    k_scan1<<<NBLK, TB>>>();
    k_scan2<<<1, 512>>>();
    k_scan3<<<gb_node, TB>>>();
    k_prep<<<PREP_BLOCKS, 320>>>(rows, cols, vals,
                                 ke0[0], ke1[0], ke0[1], ke1[1], ke0[2], ke1[2],
                                 km0[0], km1[0]);

    k_hop<0><<<SPMM_BLOCKS, 320>>>(ue, ie, out, km0[1], km1[1]);
    k_hop<1><<<SPMM_BLOCKS, 320>>>(ue, ie, out, km0[2], km1[2]);
    k_hop<2><<<SPMM_BLOCKS, 320>>>(ue, ie, out, 0u, 0u);
}

// round 15
// speedup vs baseline: 1.3629x; 1.3629x over previous
#include <cuda_runtime.h>
#include <cstdint>

#define NUSERS 100000
#define NITEMS 200000
#define NNODES 300000
#define DIM 64
#define ROWSTRIDE 256            // LEVELS * DIM
#define NNZ_E 1200000
#define NHOPS 3
#define INV_MESS_KEEP 1.1111112f // fp32(1/0.9)

#define SCAN_BLK 1024
#define NBLK ((NNODES + SCAN_BLK - 1) / SCAN_BLK)   // 293

// Scratch (__device__ globals; no allocations allowed). ~21 MB total.
__device__ unsigned g_deg[NNODES];        // degree histogram, then scatter cursor
__device__ unsigned g_rowptr[NNODES + 1]; // CSR row pointers
__device__ unsigned g_bsum[NBLK];         // scan block sums
__device__ float4   g_ew3[NNZ_E];         // CSR-ordered {w_hop0, w_hop1, w_hop2, bitcast(col)}

// ---------------------------------------------------------------------------
// Threefry-2x32 (JAX partitionable mode) — validated bit-exact (rel_err 7e-8)
// ---------------------------------------------------------------------------
__host__ __device__ __forceinline__ uint32_t rotl32(uint32_t x, int r) {
#ifdef __CUDA_ARCH__
    return __funnelshift_l(x, x, r);
#else
    return (x << r) | (x >> (32 - r));
#endif
}

__host__ __device__ __forceinline__ void threefry2x32(
    uint32_t k0, uint32_t k1, uint32_t x0, uint32_t x1,
    uint32_t& o0, uint32_t& o1)
{
    uint32_t ks2 = k0 ^ k1 ^ 0x1BD11BDAu;
    x0 += k0; x1 += k1;
#define TF_R(r) { x0 += x1; x1 = rotl32(x1, r); x1 ^= x0; }
    TF_R(13) TF_R(15) TF_R(26) TF_R(6)
    x0 += k1;  x1 += ks2 + 1u;
    TF_R(17) TF_R(29) TF_R(16) TF_R(24)
    x0 += ks2; x1 += k0 + 2u;
    TF_R(13) TF_R(15) TF_R(26) TF_R(6)
    x0 += k0;  x1 += k1 + 3u;
    TF_R(17) TF_R(29) TF_R(16) TF_R(24)
    x0 += k1;  x1 += ks2 + 4u;
    TF_R(13) TF_R(15) TF_R(26) TF_R(6)
    x0 += ks2; x1 += k0 + 5u;
#undef TF_R
    o0 = x0; o1 = x1;
}

// FOUR independent ciphers interleaved in one basic block: the compiler can
// schedule 4 chains -> ~12 issuable instrs per 8-cycle dependence window
// (vs ~6 for 2 chains), saturating the warp's issue slots.
__device__ __forceinline__ void threefry_x4(
    uint32_t k0, uint32_t k1,
    uint32_t c0, uint32_t c1, uint32_t c2, uint32_t c3,
    uint32_t& r0, uint32_t& r1, uint32_t& r2, uint32_t& r3)
{
    uint32_t ks2 = k0 ^ k1 ^ 0x1BD11BDAu;
    uint32_t a0 = k0, b0 = c0 + k1;
    uint32_t a1 = k0, b1 = c1 + k1;
    uint32_t a2 = k0, b2 = c2 + k1;
    uint32_t a3 = k0, b3 = c3 + k1;
#define TF4(r) \
    a0 += b0; b0 = rotl32(b0, r); b0 ^= a0; \
    a1 += b1; b1 = rotl32(b1, r); b1 ^= a1; \
    a2 += b2; b2 = rotl32(b2, r); b2 ^= a2; \
    a3 += b3; b3 = rotl32(b3, r); b3 ^= a3;
#define INJ4(ka, kb) \
    a0 += (ka); b0 += (kb); a1 += (ka); b1 += (kb); \
    a2 += (ka); b2 += (kb); a3 += (ka); b3 += (kb);
    TF4(13) TF4(15) TF4(26) TF4(6)
    INJ4(k1, ks2 + 1u)
    TF4(17) TF4(29) TF4(16) TF4(24)
    INJ4(ks2, k0 + 2u)
    TF4(13) TF4(15) TF4(26) TF4(6)
    INJ4(k0, k1 + 3u)
    TF4(17) TF4(29) TF4(16) TF4(24)
    INJ4(k1, ks2 + 4u)
    TF4(13) TF4(15) TF4(26) TF4(6)
    INJ4(ks2, k0 + 5u)
#undef TF4
#undef INJ4
    r0 = a0 ^ b0; r1 = a1 ^ b1; r2 = a2 ^ b2; r3 = a3 ^ b3;
}

__device__ __forceinline__ uint32_t tf_bits(uint32_t k0, uint32_t k1, uint32_t i) {
    uint32_t a, b;
    threefry2x32(k0, k1, 0u, i, a, b);
    return a ^ b;
}

__device__ __forceinline__ float bits_to_u01(uint32_t bits) {
    return __uint_as_float((bits >> 9) | 0x3f800000u) - 1.0f;
}

// ---------------------------------------------------------------------------
// CSR build: zero -> histogram -> 2-level exclusive scan -> scatter(+edge RNG)
// ---------------------------------------------------------------------------
__global__ void __launch_bounds__(256)
k_zero()
{
    unsigned i = blockIdx.x * blockDim.x + threadIdx.x;
    if (i < NNODES) g_deg[i] = 0u;
}

__global__ void __launch_bounds__(256)
k_hist(const int* __restrict__ rows)
{
    unsigned e = blockIdx.x * blockDim.x + threadIdx.x;
    if (e >= NNZ_E) return;
    atomicAdd(&g_deg[rows[e]], 1u);
}

__global__ void __launch_bounds__(256)
k_scan1()
{
    __shared__ unsigned warp_sums[8];
    unsigned b = blockIdx.x;
    unsigned base = b * SCAN_BLK + threadIdx.x * 4u;
    unsigned v[4];
#pragma unroll
    for (int i = 0; i < 4; i++) {
        unsigned idx = base + i;
        v[i] = (idx < NNODES) ? g_deg[idx] : 0u;
    }
    unsigned tsum = v[0] + v[1] + v[2] + v[3];
    unsigned lane = threadIdx.x & 31u, wid = threadIdx.x >> 5;
    unsigned x = tsum;
#pragma unroll
    for (int o = 1; o < 32; o <<= 1) {
        unsigned y = __shfl_up_sync(0xFFFFFFFFu, x, o);
        if (lane >= (unsigned)o) x += y;
    }
    if (lane == 31) warp_sums[wid] = x;
    __syncthreads();
    if (wid == 0) {
        unsigned s = (lane < 8) ? warp_sums[lane] : 0u;
#pragma unroll
        for (int o = 1; o < 8; o <<= 1) {
            unsigned y = __shfl_up_sync(0xFFFFFFFFu, s, o);
            if (lane >= (unsigned)o) s += y;
        }
        if (lane < 8) warp_sums[lane] = s;
    }
    __syncthreads();
    unsigned warp_off = (wid > 0) ? warp_sums[wid - 1] : 0u;
    unsigned run = warp_off + (x - tsum);
#pragma unroll
    for (int i = 0; i < 4; i++) {
        unsigned idx = base + i;
        if (idx < NNODES) g_rowptr[idx] = run;
        run += v[i];
    }
    if (threadIdx.x == 255) g_bsum[b] = warp_sums[7];
}

__global__ void __launch_bounds__(512)
k_scan2()
{
    __shared__ unsigned sm[512];
    unsigned t = threadIdx.x;
    sm[t] = (t < NBLK) ? g_bsum[t] : 0u;
    __syncthreads();
#pragma unroll
    for (int o = 1; o < 512; o <<= 1) {
        unsigned y = (t >= (unsigned)o) ? sm[t - o] : 0u;
        __syncthreads();
        sm[t] += y;
        __syncthreads();
    }
    if (t < NBLK) g_bsum[t] = (t == 0) ? 0u : sm[t - 1];
}

__global__ void __launch_bounds__(256)
k_scan3()
{
    unsigned i = blockIdx.x * blockDim.x + threadIdx.x;
    if (i < NNODES) {
        g_rowptr[i] += g_bsum[i >> 10];
        g_deg[i] = 0u;                     // reuse as scatter cursor
    }
    if (i == 0) g_rowptr[NNODES] = NNZ_E;
}

// scatter + ALL-HOP edge dropout RNG; writes CSR-ordered {w0,w1,w2,col}
__global__ void __launch_bounds__(256)
k_scatter(const int* __restrict__ rows, const int* __restrict__ cols,
          const float* __restrict__ vals,
          uint32_t ka0, uint32_t ka1, uint32_t kb0, uint32_t kb1,
          uint32_t kc0, uint32_t kc1)
{
    unsigned e = blockIdx.x * blockDim.x + threadIdx.x;
    if (e >= NNZ_E) return;
    int r = rows[e];
    float v2 = vals[e] * 2.0f;
    uint32_t b0 = tf_bits(ka0, ka1, e);
    uint32_t b1 = tf_bits(kb0, kb1, e);
    uint32_t b2 = tf_bits(kc0, kc1, e);
    float4 ew;
    ew.x = (b0 & 0x80000000u) ? v2 : 0.0f;   // u >= 0.5 <=> top bit (exact)
    ew.y = (b1 & 0x80000000u) ? v2 : 0.0f;
    ew.z = (b2 & 0x80000000u) ? v2 : 0.0f;
    ew.w = __int_as_float(cols[e]);
    unsigned pos = g_rowptr[r] + atomicAdd(&g_deg[r], 1u);
    g_ew3[pos] = ew;
}

// ---------------------------------------------------------------------------
// Fused SpMM + message dropout. ONE warp per TWO rows, float2 per lane per
// row. 4 interleaved cipher chains/lane (issue-saturating) + 2 independent
// edge/gather chains per warp (better latency hiding, smaller degree tail).
// ---------------------------------------------------------------------------
template <int HOP>
__global__ void __launch_bounds__(256)
k_spmm_fused(const float* __restrict__ ue, const float* __restrict__ ie,
             float* __restrict__ out, uint32_t km0, uint32_t km1)
{
    unsigned gw = (blockIdx.x * blockDim.x + threadIdx.x) >> 5;  // warp id
    unsigned r0 = gw * 2u;                   // rows r0, r0+1 (exact: 150K warps)
    if (r0 >= NNODES) return;
    unsigned lane = threadIdx.x & 31u;

    // issue rowptr loads immediately (scoreboarded)
    unsigned s0 = __ldg(&g_rowptr[r0]);
    unsigned e0 = __ldg(&g_rowptr[r0 + 1]);
    unsigned e1 = __ldg(&g_rowptr[r0 + 2]);
    unsigned s1 = e0;

    // --- hoisted message-dropout RNG: 4 interleaved chains, pure ALU ---
    unsigned j0 = r0 * 64u + lane * 2u;      // row r0 elements j0, j0+1
    uint32_t m0, m1, m2, m3;                 // row r0+1: j0+64, j0+65
    threefry_x4(km0, km1, j0, j0 + 1u, j0 + 64u, j0 + 65u, m0, m1, m2, m3);
    float keep00 = (bits_to_u01(m0) < 0.9f) ? INV_MESS_KEEP : 0.0f;
    float keep01 = (bits_to_u01(m1) < 0.9f) ? INV_MESS_KEEP : 0.0f;
    float keep10 = (bits_to_u01(m2) < 0.9f) ? INV_MESS_KEEP : 0.0f;
    float keep11 = (bits_to_u01(m3) < 0.9f) ? INV_MESS_KEEP : 0.0f;

    float2 acc0 = make_float2(0.f, 0.f);
    float2 acc1 = make_float2(0.f, 0.f);
    const float* src_base = out + (size_t)HOP * DIM;   // when HOP>0

    auto wsel = [](const float4& e) {
        return (HOP == 0) ? e.x : (HOP == 1) ? e.y : e.z;
    };
    auto srow_of = [&](int c) -> const float* {
        if (HOP == 0)
            return (c < NUSERS) ? (ue + (size_t)c * DIM)
                                : (ie + (size_t)(c - NUSERS) * DIM);
        return src_base + (size_t)c * ROWSTRIDE;
    };

    const float4 z4 = make_float4(0.f, 0.f, 0.f, 0.f);
    unsigned p0 = s0, p1 = s1;
    while (p0 < e0 || p1 < e1) {
        // 2+2 independent edge loads (broadcast; all lanes same address)
        float4 a0 = (p0      < e0) ? g_ew3[p0]      : z4;
        float4 a1 = (p0 + 1u < e0) ? g_ew3[p0 + 1u] : z4;
        float4 b0 = (p1      < e1) ? g_ew3[p1]      : z4;
        float4 b1 = (p1 + 1u < e1) ? g_ew3[p1 + 1u] : z4;
        float wa0 = wsel(a0), wa1 = wsel(a1), wb0 = wsel(b0), wb1 = wsel(b1);
        // 4 independent gathers
        float2 sa0 = make_float2(0.f, 0.f), sa1 = sa0, sb0 = sa0, sb1 = sa0;
        if (wa0 != 0.f) sa0 = *reinterpret_cast<const float2*>(srow_of(__float_as_int(a0.w)) + lane * 2u);
        if (wa1 != 0.f) sa1 = *reinterpret_cast<const float2*>(srow_of(__float_as_int(a1.w)) + lane * 2u);
        if (wb0 != 0.f) sb0 = *reinterpret_cast<const float2*>(srow_of(__float_as_int(b0.w)) + lane * 2u);
        if (wb1 != 0.f) sb1 = *reinterpret_cast<const float2*>(srow_of(__float_as_int(b1.w)) + lane * 2u);
        acc0.x += wa0 * sa0.x + wa1 * sa1.x;
        acc0.y += wa0 * sa0.y + wa1 * sa1.y;
        acc1.x += wb0 * sb0.x + wb1 * sb1.x;
        acc1.y += wb0 * sb0.y + wb1 * sb1.y;
        p0 += 2u; p1 += 2u;
    }

    // epilogue: apply precomputed keep factors, store both rows
    float* orow0 = out + (size_t)r0 * ROWSTRIDE;
    float* orow1 = orow0 + ROWSTRIDE;
    float2 res0 = make_float2(acc0.x * keep00, acc0.y * keep01);
    float2 res1 = make_float2(acc1.x * keep10, acc1.y * keep11);
    *reinterpret_cast<float2*>(orow0 + (size_t)(HOP + 1) * DIM + lane * 2u) = res0;
    *reinterpret_cast<float2*>(orow1 + (size_t)(HOP + 1) * DIM + lane * 2u) = res1;

    if (HOP == 0) {
        // emit level-0 copies (rows r0, r0+1 of concat(ue, ie))
        const float* er0 = (r0 < NUSERS) ? (ue + (size_t)r0 * DIM)
                                         : (ie + (size_t)(r0 - NUSERS) * DIM);
        unsigned r1n = r0 + 1u;
        const float* er1 = (r1n < NUSERS) ? (ue + (size_t)r1n * DIM)
                                          : (ie + (size_t)(r1n - NUSERS) * DIM);
        float2 c0 = *reinterpret_cast<const float2*>(er0 + lane * 2u);
        float2 c1 = *reinterpret_cast<const float2*>(er1 + lane * 2u);
        *reinterpret_cast<float2*>(orow0 + lane * 2u) = c0;
        *reinterpret_cast<float2*>(orow1 + lane * 2u) = c1;
    }
}

// ---------------------------------------------------------------------------
// Launch
// ---------------------------------------------------------------------------
extern "C" void kernel_launch(void* const* d_in, const int* in_sizes, int n_in,
                              void* d_out, int out_size)
{
    const float* ue = nullptr; const float* ie = nullptr;
    const float* vals = nullptr; const int* rows = nullptr; const int* cols = nullptr;
    int nnz_seen = 0;
    for (int i = 0; i < n_in; i++) {
        if (in_sizes[i] == NUSERS * DIM)      ue = (const float*)d_in[i];
        else if (in_sizes[i] == NITEMS * DIM) ie = (const float*)d_in[i];
        else if (in_sizes[i] == NNZ_E) {
            if (nnz_seen == 0)      vals = (const float*)d_in[i];
            else if (nnz_seen == 1) rows = (const int*)d_in[i];
            else                    cols = (const int*)d_in[i];
            nnz_seen++;
        }
    }
    float* out = (float*)d_out;

    // JAX key derivation (validated): base=(0,42); hk=cipher(base,(0,hop));
    // ke=cipher(hk,(0,0)), km=cipher(hk,(0,1))
    uint32_t ke0[NHOPS], ke1[NHOPS], km0[NHOPS], km1[NHOPS];
    for (int h = 0; h < NHOPS; h++) {
        uint32_t h0, h1;
        threefry2x32(0u, 42u, 0u, (uint32_t)h, h0, h1);
        threefry2x32(h0, h1, 0u, 0u, ke0[h], ke1[h]);
        threefry2x32(h0, h1, 0u, 1u, km0[h], km1[h]);
    }

    const int TB = 256;
    unsigned gb_node = (NNODES + TB - 1) / TB;
    unsigned gb_edge = (NNZ_E + TB - 1) / TB;
    unsigned gb_fuse = ((unsigned)(NNODES / 2) * 32u + TB - 1) / TB;  // 1 warp / 2 rows

    k_zero<<<gb_node, TB>>>();
    k_hist<<<gb_edge, TB>>>(rows);
    k_scan1<<<NBLK, TB>>>();
    k_scan2<<<1, 512>>>();
    k_scan3<<<gb_node, TB>>>();
    k_scatter<<<gb_edge, TB>>>(rows, cols, vals,
                               ke0[0], ke1[0], ke0[1], ke1[1], ke0[2], ke1[2]);

    k_spmm_fused<0><<<gb_fuse, TB>>>(ue, ie, out, km0[0], km1[0]);
    k_spmm_fused<1><<<gb_fuse, TB>>>(ue, ie, out, km0[1], km1[1]);
    k_spmm_fused<2><<<gb_fuse, TB>>>(ue, ie, out, km0[2], km1[2]);
}